// round 9
// baseline (speedup 1.0000x reference)
#include <cuda_runtime.h>
#include <cuda_fp16.h>

#define DM 256
#define NH 4
#define DH 64
#define BB 4
#define TT 512
#define SS 512
#define BHN 16
#define MM 2048           // B*T rows
#define PSZ (MM * DM)     // one partial buffer

// Scratch (no allocs -> device globals)
__device__ unsigned int g_Qh[BHN * TT * 32];  // half2 [bh][t][d/2]
__device__ unsigned int g_Kh[BHN * SS * 32];  // half2 [bh][s][d/2]
__device__ float g_V[BHN * SS * DH];          // f32   [bh][s][d]
__device__ float g_att[BB * TT * DM];         // attended [b][t][h*64+d]
__device__ float g_P[6 * PSZ];                // split-K partials (reused for out)

// ---- packed helpers -------------------------------------------------------
__device__ __forceinline__ unsigned long long pack2(float x, float y) {
    unsigned long long r;
    asm("mov.b64 %0, {%1, %2};" : "=l"(r) : "f"(x), "f"(y));
    return r;
}
__device__ __forceinline__ float2 unpack2(unsigned long long v) {
    float2 r;
    asm("mov.b64 {%0, %1}, %2;" : "=f"(r.x), "=f"(r.y) : "l"(v));
    return r;
}
__device__ __forceinline__ unsigned long long fma2(unsigned long long a,
                                                   unsigned long long b,
                                                   unsigned long long c) {
    unsigned long long d;
    asm("fma.rn.f32x2 %0, %1, %2, %3;" : "=l"(d) : "l"(a), "l"(b), "l"(c));
    return d;
}
__device__ __forceinline__ unsigned int htanh2(unsigned int x) {
    unsigned int y;
    asm("tanh.approx.f16x2 %0, %1;" : "=r"(y) : "r"(x));
    return y;
}
__device__ __forceinline__ unsigned int hadd2u(unsigned int a, unsigned int b) {
    unsigned int y;
    asm("add.rn.f16x2 %0, %1, %2;" : "=r"(y) : "r"(a), "r"(b));
    return y;
}
__device__ __forceinline__ float2 h2f2(unsigned int h) {
    __half2 v = *reinterpret_cast<__half2*>(&h);
    return __half22float2(v);
}

// 8-element weighted tanh dot: sum_j v[j]*tanh(q[j]+k[j]) for 8 halves
__device__ __forceinline__ float dot8(uint4 q, uint4 k, float4 v0, float4 v1) {
    float2 t0 = h2f2(htanh2(hadd2u(q.x, k.x)));
    float2 t1 = h2f2(htanh2(hadd2u(q.y, k.y)));
    float2 t2 = h2f2(htanh2(hadd2u(q.z, k.z)));
    float2 t3 = h2f2(htanh2(hadd2u(q.w, k.w)));
    float a = v0.x * t0.x + v0.y * t0.y + v0.z * t1.x + v0.w * t1.y;
    a += v1.x * t2.x + v1.y * t2.y + v1.z * t3.x + v1.w * t3.y;
    return a;
}

// ---------------------------------------------------------------------------
// Split-K GEMM: P[m][n] = sum_{k in half kh} A[m][k]*W[n][k].
// 64x64 tile, 256 thr, 4x4 micro (f32x2), double-buffered smem + prefetch.
// mode_base 0 (projections): z = proj*2 + kh, proj 0/1/2 = Q/K/V.
// mode_base 3 (out proj):    z = kh, A = g_att, W = w_o (via q_in slot).
// All write f32 partials to g_P[z].
// ---------------------------------------------------------------------------
__global__ __launch_bounds__(256) void gemm_sk(const float* __restrict__ q_in,
                                               const float* __restrict__ k_in,
                                               const float* __restrict__ v_in,
                                               const float* __restrict__ w_q,
                                               const float* __restrict__ w_k,
                                               const float* __restrict__ w_v,
                                               int mode_base) {
    __shared__ float Ast[2][8 * 68 * 2];   // [k][row] pitch 68, 2 bufs of 16k
    __shared__ float Wst[2][8 * 68 * 2];

    const int z = blockIdx.z;
    int kh;
    const float *A, *W;
    if (mode_base == 3) {
        kh = z; A = g_att; W = q_in;      // q_in slot carries w_o
    } else {
        int proj = z >> 1; kh = z & 1;
        A = (proj == 0) ? q_in : (proj == 1) ? k_in : v_in;
        W = (proj == 0) ? w_q : (proj == 1) ? w_k : w_v;
    }
    float* P = g_P + (size_t)z * PSZ;

    const int m0 = blockIdx.x * 64;
    const int n0 = blockIdx.y * 64;
    const int tid = threadIdx.x;
    const int tx = tid & 15;
    const int ty = tid >> 4;

    const int lr = tid >> 2;          // 0..63 row within tile
    const int lc = (tid & 3) * 4;     // 0..12 k within chunk
    const float* Aptr = A + (size_t)(m0 + lr) * DM + kh * 128 + lc;
    const float* Wptr = W + (size_t)(n0 + lr) * DM + kh * 128 + lc;

    unsigned long long acc[4][2];
#pragma unroll
    for (int i = 0; i < 4; i++) { acc[i][0] = 0ull; acc[i][1] = 0ull; }

    float4 ra = *(const float4*)Aptr;
    float4 rw = *(const float4*)Wptr;
#pragma unroll
    for (int j = 0; j < 4; j++) {
        Ast[0][(lc + j) * 68 + lr] = ((const float*)&ra)[j];
        Wst[0][(lc + j) * 68 + lr] = ((const float*)&rw)[j];
    }
    ra = *(const float4*)(Aptr + 16);
    rw = *(const float4*)(Wptr + 16);

#pragma unroll 1
    for (int c = 0; c < 8; c++) {       // 8 chunks of 16 k = 128 k
        const int p = c & 1;
        __syncthreads();
        if (c < 7) {
#pragma unroll
            for (int j = 0; j < 4; j++) {
                Ast[p ^ 1][(lc + j) * 68 + lr] = ((const float*)&ra)[j];
                Wst[p ^ 1][(lc + j) * 68 + lr] = ((const float*)&rw)[j];
            }
        }
        if (c < 6) {
            ra = *(const float4*)(Aptr + (c + 2) * 16);
            rw = *(const float4*)(Wptr + (c + 2) * 16);
        }
#pragma unroll
        for (int kk = 0; kk < 16; kk++) {
            float4 a4 = *(const float4*)&Ast[p][kk * 68 + ty * 4];
            ulonglong2 w2 = *(const ulonglong2*)&Wst[p][kk * 68 + tx * 4];
            unsigned long long aa;
            aa = pack2(a4.x, a4.x); acc[0][0] = fma2(aa, w2.x, acc[0][0]); acc[0][1] = fma2(aa, w2.y, acc[0][1]);
            aa = pack2(a4.y, a4.y); acc[1][0] = fma2(aa, w2.x, acc[1][0]); acc[1][1] = fma2(aa, w2.y, acc[1][1]);
            aa = pack2(a4.z, a4.z); acc[2][0] = fma2(aa, w2.x, acc[2][0]); acc[2][1] = fma2(aa, w2.y, acc[2][1]);
            aa = pack2(a4.w, a4.w); acc[3][0] = fma2(aa, w2.x, acc[3][0]); acc[3][1] = fma2(aa, w2.y, acc[3][1]);
        }
    }

#pragma unroll
    for (int i = 0; i < 4; i++) {
        int m = m0 + ty * 4 + i;
        float2 c01 = unpack2(acc[i][0]);
        float2 c23 = unpack2(acc[i][1]);
        *(float4*)&P[(size_t)m * DM + n0 + tx * 4] =
            make_float4(c01.x, c01.y, c23.x, c23.y);
    }
}

// ---------------------------------------------------------------------------
// Combine split-K partials for projections: sum g_P[2p] + g_P[2p+1], apply
// epilogue (h16 pack + scatter for Q/K, f32 scatter for V).
// Grid (256, 3): block = 8 m-rows x 256 n, thread = 8 consecutive n.
// ---------------------------------------------------------------------------
__global__ __launch_bounds__(256) void combine_proj() {
    const int proj = blockIdx.y;
    const int m = blockIdx.x * 8 + (threadIdx.x >> 5);
    const int n = (threadIdx.x & 31) * 8;

    const float* P0 = g_P + (size_t)(proj * 2) * PSZ + (size_t)m * DM + n;
    const float* P1 = P0 + PSZ;

    float4 a0 = *(const float4*)P0;
    float4 a1 = *(const float4*)(P0 + 4);
    float4 b0 = *(const float4*)P1;
    float4 b1 = *(const float4*)(P1 + 4);
    float v0 = a0.x + b0.x, v1 = a0.y + b0.y, v2 = a0.z + b0.z, v3 = a0.w + b0.w;
    float v4 = a1.x + b1.x, v5 = a1.y + b1.y, v6 = a1.z + b1.z, v7 = a1.w + b1.w;

    const int bb = m >> 9, t = m & 511;
    const int hh = n >> 6, d = n & 63;

    if (proj < 2) {
        unsigned int* dst = (proj == 0) ? g_Qh : g_Kh;
        __half2 h0 = __floats2half2_rn(v0, v1);
        __half2 h1 = __floats2half2_rn(v2, v3);
        __half2 h2 = __floats2half2_rn(v4, v5);
        __half2 h3 = __floats2half2_rn(v6, v7);
        uint4 u = make_uint4(*(unsigned int*)&h0, *(unsigned int*)&h1,
                             *(unsigned int*)&h2, *(unsigned int*)&h3);
        *(uint4*)&dst[((size_t)(bb * NH + hh) * TT + t) * 32 + (d >> 1)] = u;
    } else {
        float* base = &g_V[((size_t)(bb * NH + hh) * TT + t) * DH + d];
        *(float4*)base = make_float4(v0, v1, v2, v3);
        *(float4*)(base + 4) = make_float4(v4, v5, v6, v7);
    }
}

// Combine split-K partials for output projection: out = g_P[0] + g_P[1].
__global__ __launch_bounds__(256) void combine_out(float* __restrict__ out) {
    const int m = blockIdx.x * 8 + (threadIdx.x >> 5);
    const int n = (threadIdx.x & 31) * 8;
    const float* P0 = g_P + (size_t)m * DM + n;
    const float* P1 = P0 + PSZ;
    float4 a0 = *(const float4*)P0;
    float4 a1 = *(const float4*)(P0 + 4);
    float4 b0 = *(const float4*)P1;
    float4 b1 = *(const float4*)(P1 + 4);
    float* o = out + (size_t)m * DM + n;
    *(float4*)o = make_float4(a0.x + b0.x, a0.y + b0.y, a0.z + b0.z, a0.w + b0.w);
    *(float4*)(o + 4) = make_float4(a1.x + b1.x, a1.y + b1.y, a1.z + b1.z, a1.w + b1.w);
}

// ---------------------------------------------------------------------------
// Fused scores(tanh, h16) + softmax + AV. Block = (bh, 32 t rows), full S=512.
// Phase 1: warp w owns s in [w*64, w*64+64) as 8 groups of 8 streams.
// Phase 4: AV with 64-row V tiles (half the syncthreads of 32-row tiles).
// ---------------------------------------------------------------------------
#define SCP 516
__global__ __launch_bounds__(256, 2) void attn_fused_kernel(const float* __restrict__ v_a,
                                                            float* __restrict__ attn) {
    extern __shared__ float sm[];
    float* sc = sm;              // 32 * 516
    float* Bs = sm + 32 * SCP;   // 64 * 68

    __shared__ float vas[64];

    const int bh = blockIdx.x;
    const int t0 = blockIdx.y * 32;
    const int h = bh & 3;
    const int tid = threadIdx.x;
    const int lane = tid & 31;
    const int w = tid >> 5;

    if (tid < 16) ((float4*)vas)[tid] = ((const float4*)(v_a + h * DH))[tid];
    __syncthreads();

    // ---- Phase 1: scores -> sc (8 s-streams per warp) -------------------------
    {
        uint4 qreg[8];
        const uint4* qg = (const uint4*)(g_Qh + ((size_t)bh * TT + t0 + lane) * 32);
#pragma unroll
        for (int i = 0; i < 8; i++) qreg[i] = qg[i];

#pragma unroll 1
        for (int g = 0; g < 8; g++) {
            const int sl = w * 64 + g * 8;
            const uint4* K0 = (const uint4*)(g_Kh + ((size_t)bh * SS + sl) * 32);
            const uint4* K1 = K0 + 8;
            const uint4* K2 = K0 + 16;
            const uint4* K3 = K0 + 24;
            const uint4* K4 = K0 + 32;
            const uint4* K5 = K0 + 40;
            const uint4* K6 = K0 + 48;
            const uint4* K7 = K0 + 56;
            float a0 = 0.f, a1 = 0.f, a2 = 0.f, a3 = 0.f;
            float a4 = 0.f, a5 = 0.f, a6 = 0.f, a7 = 0.f;
#pragma unroll
            for (int i = 0; i < 8; i++) {
                float4 v0 = *(const float4*)&vas[i * 8];
                float4 v1 = *(const float4*)&vas[i * 8 + 4];
                uint4 q = qreg[i];
                a0 += dot8(q, K0[i], v0, v1);
                a1 += dot8(q, K1[i], v0, v1);
                a2 += dot8(q, K2[i], v0, v1);
                a3 += dot8(q, K3[i], v0, v1);
                a4 += dot8(q, K4[i], v0, v1);
                a5 += dot8(q, K5[i], v0, v1);
                a6 += dot8(q, K6[i], v0, v1);
                a7 += dot8(q, K7[i], v0, v1);
            }
            *(float4*)&sc[lane * SCP + sl] =
                make_float4(a0 * 0.125f, a1 * 0.125f, a2 * 0.125f, a3 * 0.125f);
            *(float4*)&sc[lane * SCP + sl + 4] =
                make_float4(a4 * 0.125f, a5 * 0.125f, a6 * 0.125f, a7 * 0.125f);
        }
    }
    __syncthreads();

    // ---- Phase 2: softmax (warp w -> rows w*4..w*4+3) --------------------------
#pragma unroll 1
    for (int q = 0; q < 4; q++) {
        int r = w * 4 + q;
        float4* row = (float4*)&sc[r * SCP];
        float4 x0 = row[lane], x1 = row[lane + 32], x2 = row[lane + 64], x3 = row[lane + 96];
        float m = fmaxf(fmaxf(fmaxf(x0.x, x0.y), fmaxf(x0.z, x0.w)),
                        fmaxf(fmaxf(x1.x, x1.y), fmaxf(x1.z, x1.w)));
        m = fmaxf(m, fmaxf(fmaxf(fmaxf(x2.x, x2.y), fmaxf(x2.z, x2.w)),
                           fmaxf(fmaxf(x3.x, x3.y), fmaxf(x3.z, x3.w))));
#pragma unroll
        for (int o = 16; o; o >>= 1) m = fmaxf(m, __shfl_xor_sync(0xffffffffu, m, o));
        x0.x = __expf(x0.x - m); x0.y = __expf(x0.y - m); x0.z = __expf(x0.z - m); x0.w = __expf(x0.w - m);
        x1.x = __expf(x1.x - m); x1.y = __expf(x1.y - m); x1.z = __expf(x1.z - m); x1.w = __expf(x1.w - m);
        x2.x = __expf(x2.x - m); x2.y = __expf(x2.y - m); x2.z = __expf(x2.z - m); x2.w = __expf(x2.w - m);
        x3.x = __expf(x3.x - m); x3.y = __expf(x3.y - m); x3.z = __expf(x3.z - m); x3.w = __expf(x3.w - m);
        float s = (x0.x + x0.y + x0.z + x0.w) + (x1.x + x1.y + x1.z + x1.w)
                + (x2.x + x2.y + x2.z + x2.w) + (x3.x + x3.y + x3.z + x3.w);
#pragma unroll
        for (int o = 16; o; o >>= 1) s += __shfl_xor_sync(0xffffffffu, s, o);
        float inv = 1.0f / s;
        x0.x *= inv; x0.y *= inv; x0.z *= inv; x0.w *= inv;
        x1.x *= inv; x1.y *= inv; x1.z *= inv; x1.w *= inv;
        x2.x *= inv; x2.y *= inv; x2.z *= inv; x2.w *= inv;
        x3.x *= inv; x3.y *= inv; x3.z *= inv; x3.w *= inv;
        row[lane] = x0; row[lane + 32] = x1; row[lane + 64] = x2; row[lane + 96] = x3;
    }
    __syncthreads();

    // ---- Phase 3: write attn ----------------------------------------------------
    {
        float* arow = attn + ((size_t)bh * TT + t0) * SS;
        for (int i = tid; i < 32 * 128; i += 256) {
            int r = i >> 7, c = i & 127;
            *(float4*)&arow[(size_t)r * SS + c * 4] = *(const float4*)&sc[r * SCP + c * 4];
        }
    }

    // ---- Phase 4: AV (32t x 64d, 64-row V tiles, micro 2t x 4d) ------------------
    const float* Vg = g_V + (size_t)bh * SS * DH;
    const int tx = tid & 15;    // d/4
    const int tyy = tid >> 4;   // t/2  (0..15)
    unsigned long long acc[2][2];
    acc[0][0] = acc[0][1] = acc[1][0] = acc[1][1] = 0ull;

#pragma unroll 1
    for (int s0 = 0; s0 < SS; s0 += 64) {
        __syncthreads();
        for (int i = tid; i < 1024; i += 256) {
            int rr = i >> 4, cc = i & 15;
            *(float4*)&Bs[rr * 68 + cc * 4] = *(const float4*)&Vg[(size_t)(s0 + rr) * DH + cc * 4];
        }
        __syncthreads();
#pragma unroll 8
        for (int kk = 0; kk < 64; kk++) {
            ulonglong2 b2 = *(const ulonglong2*)&Bs[kk * 68 + tx * 4];
            float a0 = sc[(size_t)(tyy * 2) * SCP + s0 + kk];
            float a1 = sc[(size_t)(tyy * 2 + 1) * SCP + s0 + kk];
            unsigned long long aa;
            aa = pack2(a0, a0); acc[0][0] = fma2(aa, b2.x, acc[0][0]); acc[0][1] = fma2(aa, b2.y, acc[0][1]);
            aa = pack2(a1, a1); acc[1][0] = fma2(aa, b2.x, acc[1][0]); acc[1][1] = fma2(aa, b2.y, acc[1][1]);
        }
    }

    {
        const int b = bh >> 2;
#pragma unroll
        for (int i = 0; i < 2; i++) {
            int t = t0 + tyy * 2 + i;
            float2 c01 = unpack2(acc[i][0]);
            float2 c23 = unpack2(acc[i][1]);
            *(float4*)&g_att[((size_t)(b * TT + t)) * DM + h * DH + tx * 4] =
                make_float4(c01.x, c01.y, c23.x, c23.y);
        }
    }
}

// ---------------------------------------------------------------------------
extern "C" void kernel_launch(void* const* d_in, const int* in_sizes, int n_in,
                              void* d_out, int out_size) {
    const float* query = (const float*)d_in[0];
    const float* key   = (const float*)d_in[1];
    const float* value = (const float*)d_in[2];
    const float* w_q   = (const float*)d_in[3];
    const float* w_k   = (const float*)d_in[4];
    const float* w_v   = (const float*)d_in[5];
    const float* v_a   = (const float*)d_in[6];
    const float* w_o   = (const float*)d_in[7];

    float* out  = (float*)d_out;
    float* attn = out + (size_t)BB * TT * DM;

    // Q/K/V projections, split-K=2: z = proj*2 + khalf -> g_P[z]
    gemm_sk<<<dim3(32, 4, 6), 256>>>(query, key, value, w_q, w_k, w_v, 0);
    combine_proj<<<dim3(256, 3), 256>>>();

    // fused additive-attention (scores + softmax + AV)
    const int dyn = (32 * SCP + 64 * 68) * sizeof(float);   // ~83.5 KB
    cudaFuncSetAttribute(attn_fused_kernel,
                         cudaFuncAttributeMaxDynamicSharedMemorySize, dyn);
    attn_fused_kernel<<<dim3(BHN, TT / 32), 256, dyn>>>(v_a, attn);

    // output projection, split-K=2 (w_o via q_in slot) -> g_P[0..1]
    gemm_sk<<<dim3(32, 4, 2), 256>>>(w_o, nullptr, nullptr, nullptr, nullptr, nullptr, 3);
    combine_out<<<256, 256>>>(out);
}

// round 10
// speedup vs baseline: 1.0457x; 1.0457x over previous
#include <cuda_runtime.h>
#include <cuda_fp16.h>

#define DM 256
#define NH 4
#define DH 64
#define BB 4
#define TT 512
#define SS 512
#define BHN 16

// Scratch (no allocs -> device globals)
__device__ unsigned int g_Qh[BHN * TT * 32];  // half2 [bh][t][d/2]
__device__ unsigned int g_Kh[BHN * SS * 32];  // half2 [bh][s][d/2]
__device__ float g_V[BHN * SS * DH];          // f32   [bh][s][d]
__device__ float g_att[BB * TT * DM];         // attended [b][t][h*64+d]

// ---- packed helpers -------------------------------------------------------
__device__ __forceinline__ unsigned long long pack2(float x, float y) {
    unsigned long long r;
    asm("mov.b64 %0, {%1, %2};" : "=l"(r) : "f"(x), "f"(y));
    return r;
}
__device__ __forceinline__ float2 unpack2(unsigned long long v) {
    float2 r;
    asm("mov.b64 {%0, %1}, %2;" : "=f"(r.x), "=f"(r.y) : "l"(v));
    return r;
}
__device__ __forceinline__ unsigned long long fma2(unsigned long long a,
                                                   unsigned long long b,
                                                   unsigned long long c) {
    unsigned long long d;
    asm("fma.rn.f32x2 %0, %1, %2, %3;" : "=l"(d) : "l"(a), "l"(b), "l"(c));
    return d;
}
__device__ __forceinline__ unsigned int htanh2(unsigned int x) {
    unsigned int y;
    asm("tanh.approx.f16x2 %0, %1;" : "=r"(y) : "r"(x));
    return y;
}
__device__ __forceinline__ unsigned int hadd2u(unsigned int a, unsigned int b) {
    unsigned int y;
    asm("add.rn.f16x2 %0, %1, %2;" : "=r"(y) : "r"(a), "r"(b));
    return y;
}
__device__ __forceinline__ unsigned int hmul2u(unsigned int a, unsigned int b) {
    unsigned int y;
    asm("mul.rn.f16x2 %0, %1, %2;" : "=r"(y) : "r"(a), "r"(b));
    return y;
}
__device__ __forceinline__ unsigned int hfma2u(unsigned int a, unsigned int b, unsigned int c) {
    unsigned int y;
    asm("fma.rn.f16x2 %0, %1, %2, %3;" : "=r"(y) : "r"(a), "r"(b), "r"(c));
    return y;
}
__device__ __forceinline__ float2 h2f2(unsigned int h) {
    __half2 v = *reinterpret_cast<__half2*>(&h);
    return __half22float2(v);
}

// 8-element weighted tanh dot, fp16 product chain (len 4), fp32 result.
// 15 issue slots per 8 elements (vs 24 for the f32-accumulate variant).
__device__ __forceinline__ float dot8h(uint4 q, uint4 k, uint4 vah) {
    unsigned int t0 = htanh2(hadd2u(q.x, k.x));
    unsigned int t1 = htanh2(hadd2u(q.y, k.y));
    unsigned int t2 = htanh2(hadd2u(q.z, k.z));
    unsigned int t3 = htanh2(hadd2u(q.w, k.w));
    unsigned int c = hmul2u(vah.x, t0);
    c = hfma2u(vah.y, t1, c);
    c = hfma2u(vah.z, t2, c);
    c = hfma2u(vah.w, t3, c);
    float2 f = h2f2(c);
    return f.x + f.y;
}

// ---------------------------------------------------------------------------
// GEMM (R3 measured-good): C[m][n] = sum_k A[m][k]*W[n][k]. 64x64 tile,
// 256 thr, 4x4 micro (f32x2), double-buffered smem + prefetch.
// mode 0: -> g_Qh(h16)  1: -> g_Kh(h16)  2: -> g_V(f32)  3: g_att @ w_o.T -> C
// ---------------------------------------------------------------------------
__global__ __launch_bounds__(256) void gemm_kernel(const float* __restrict__ q_in,
                                                   const float* __restrict__ k_in,
                                                   const float* __restrict__ v_in,
                                                   const float* __restrict__ w_q,
                                                   const float* __restrict__ w_k,
                                                   const float* __restrict__ w_v,
                                                   float* __restrict__ C,
                                                   int mode_base) {
    __shared__ float Ast[2][16 * 68];
    __shared__ float Wst[2][16 * 68];

    const int mode = (mode_base == 3) ? 3 : (int)blockIdx.z;
    const float* A = (mode == 0) ? q_in : (mode == 1) ? k_in : (mode == 2) ? v_in : g_att;
    const float* W = (mode == 0) ? w_q : (mode == 1) ? w_k : (mode == 2) ? w_v : /*w_o*/ q_in;

    const int m0 = blockIdx.x * 64;
    const int n0 = blockIdx.y * 64;
    const int tid = threadIdx.x;
    const int tx = tid & 15;
    const int ty = tid >> 4;

    const int lr = tid >> 2;          // 0..63 row within tile
    const int lc = (tid & 3) * 4;     // 0..12 k within chunk
    const float* Aptr = A + (size_t)(m0 + lr) * DM + lc;
    const float* Wptr = W + (size_t)(n0 + lr) * DM + lc;

    unsigned long long acc[4][2];
#pragma unroll
    for (int i = 0; i < 4; i++) { acc[i][0] = 0ull; acc[i][1] = 0ull; }

    float4 ra = *(const float4*)Aptr;
    float4 rw = *(const float4*)Wptr;
#pragma unroll
    for (int j = 0; j < 4; j++) {
        Ast[0][(lc + j) * 68 + lr] = ((const float*)&ra)[j];
        Wst[0][(lc + j) * 68 + lr] = ((const float*)&rw)[j];
    }
    ra = *(const float4*)(Aptr + 16);
    rw = *(const float4*)(Wptr + 16);

#pragma unroll 1
    for (int c = 0; c < 16; c++) {
        const int p = c & 1;
        __syncthreads();
        if (c < 15) {
#pragma unroll
            for (int j = 0; j < 4; j++) {
                Ast[p ^ 1][(lc + j) * 68 + lr] = ((const float*)&ra)[j];
                Wst[p ^ 1][(lc + j) * 68 + lr] = ((const float*)&rw)[j];
            }
        }
        if (c < 14) {
            ra = *(const float4*)(Aptr + (c + 2) * 16);
            rw = *(const float4*)(Wptr + (c + 2) * 16);
        }
#pragma unroll
        for (int kk = 0; kk < 16; kk++) {
            float4 a4 = *(const float4*)&Ast[p][kk * 68 + ty * 4];
            ulonglong2 w2 = *(const ulonglong2*)&Wst[p][kk * 68 + tx * 4];
            unsigned long long aa;
            aa = pack2(a4.x, a4.x); acc[0][0] = fma2(aa, w2.x, acc[0][0]); acc[0][1] = fma2(aa, w2.y, acc[0][1]);
            aa = pack2(a4.y, a4.y); acc[1][0] = fma2(aa, w2.x, acc[1][0]); acc[1][1] = fma2(aa, w2.y, acc[1][1]);
            aa = pack2(a4.z, a4.z); acc[2][0] = fma2(aa, w2.x, acc[2][0]); acc[2][1] = fma2(aa, w2.y, acc[2][1]);
            aa = pack2(a4.w, a4.w); acc[3][0] = fma2(aa, w2.x, acc[3][0]); acc[3][1] = fma2(aa, w2.y, acc[3][1]);
        }
    }

    if (mode <= 1) {
        unsigned int* dst = (mode == 0) ? g_Qh : g_Kh;
        const int hh = n0 >> 6;
#pragma unroll
        for (int i = 0; i < 4; i++) {
            int m = m0 + ty * 4 + i;
            int bb = m >> 9, t = m & 511;
            float2 c01 = unpack2(acc[i][0]);
            float2 c23 = unpack2(acc[i][1]);
            __half2 h0 = __floats2half2_rn(c01.x, c01.y);
            __half2 h1 = __floats2half2_rn(c23.x, c23.y);
            uint2 u = make_uint2(*(unsigned int*)&h0, *(unsigned int*)&h1);
            *(uint2*)&dst[((size_t)(bb * NH + hh) * TT + t) * 32 + tx * 2] = u;
        }
    } else if (mode == 2) {
        const int hh = n0 >> 6;
#pragma unroll
        for (int i = 0; i < 4; i++) {
            int m = m0 + ty * 4 + i;
            int bb = m >> 9, t = m & 511;
            float2 c01 = unpack2(acc[i][0]);
            float2 c23 = unpack2(acc[i][1]);
            *(float4*)&g_V[((size_t)(bb * NH + hh) * TT + t) * DH + tx * 4] =
                make_float4(c01.x, c01.y, c23.x, c23.y);
        }
    } else {
#pragma unroll
        for (int i = 0; i < 4; i++) {
            int m = m0 + ty * 4 + i;
            float2 c01 = unpack2(acc[i][0]);
            float2 c23 = unpack2(acc[i][1]);
            *(float4*)&C[(size_t)m * DM + n0 + tx * 4] =
                make_float4(c01.x, c01.y, c23.x, c23.y);
        }
    }
}

// ---------------------------------------------------------------------------
// Fused scores(tanh, h16 chain) + softmax + AV. Block = (bh, 32 t rows).
// Phase 1: warp w owns s in [w*64, w*64+64) as 8 groups of 8 streams,
// fp16 product chains (dot8h) to cut issue pressure around MUFU.
// ---------------------------------------------------------------------------
#define SCP 516
__global__ __launch_bounds__(256, 2) void attn_fused_kernel(const float* __restrict__ v_a,
                                                            float* __restrict__ attn) {
    extern __shared__ float sm[];
    float* sc = sm;              // 32 * 516
    float* Bs = sm + 32 * SCP;   // 32 * 68

    __shared__ unsigned int vas_h[32];   // v_a as half2

    const int bh = blockIdx.x;
    const int t0 = blockIdx.y * 32;
    const int h = bh & 3;
    const int tid = threadIdx.x;
    const int lane = tid & 31;
    const int w = tid >> 5;

    if (tid < 16) {
        float4 v = ((const float4*)(v_a + h * DH))[tid];
        __half2 h0 = __floats2half2_rn(v.x, v.y);
        __half2 h1 = __floats2half2_rn(v.z, v.w);
        vas_h[tid * 2] = *(unsigned int*)&h0;
        vas_h[tid * 2 + 1] = *(unsigned int*)&h1;
    }
    __syncthreads();

    // ---- Phase 1: scores -> sc (8 s-streams per warp, h16 chains) -------------
    {
        uint4 qreg[8];
        const uint4* qg = (const uint4*)(g_Qh + ((size_t)bh * TT + t0 + lane) * 32);
#pragma unroll
        for (int i = 0; i < 8; i++) qreg[i] = qg[i];

#pragma unroll 1
        for (int g = 0; g < 8; g++) {
            const int sl = w * 64 + g * 8;
            const uint4* K0 = (const uint4*)(g_Kh + ((size_t)bh * SS + sl) * 32);
            const uint4* K1 = K0 + 8;
            const uint4* K2 = K0 + 16;
            const uint4* K3 = K0 + 24;
            const uint4* K4 = K0 + 32;
            const uint4* K5 = K0 + 40;
            const uint4* K6 = K0 + 48;
            const uint4* K7 = K0 + 56;
            float a0 = 0.f, a1 = 0.f, a2 = 0.f, a3 = 0.f;
            float a4 = 0.f, a5 = 0.f, a6 = 0.f, a7 = 0.f;
#pragma unroll
            for (int i = 0; i < 8; i++) {
                uint4 vah = *(const uint4*)&vas_h[i * 4];   // LDS.128 broadcast
                uint4 q = qreg[i];
                a0 += dot8h(q, K0[i], vah);
                a1 += dot8h(q, K1[i], vah);
                a2 += dot8h(q, K2[i], vah);
                a3 += dot8h(q, K3[i], vah);
                a4 += dot8h(q, K4[i], vah);
                a5 += dot8h(q, K5[i], vah);
                a6 += dot8h(q, K6[i], vah);
                a7 += dot8h(q, K7[i], vah);
            }
            *(float4*)&sc[lane * SCP + sl] =
                make_float4(a0 * 0.125f, a1 * 0.125f, a2 * 0.125f, a3 * 0.125f);
            *(float4*)&sc[lane * SCP + sl + 4] =
                make_float4(a4 * 0.125f, a5 * 0.125f, a6 * 0.125f, a7 * 0.125f);
        }
    }
    __syncthreads();

    // ---- Phase 2: softmax (warp w -> rows w*4..w*4+3) --------------------------
#pragma unroll 1
    for (int q = 0; q < 4; q++) {
        int r = w * 4 + q;
        float4* row = (float4*)&sc[r * SCP];
        float4 x0 = row[lane], x1 = row[lane + 32], x2 = row[lane + 64], x3 = row[lane + 96];
        float m = fmaxf(fmaxf(fmaxf(x0.x, x0.y), fmaxf(x0.z, x0.w)),
                        fmaxf(fmaxf(x1.x, x1.y), fmaxf(x1.z, x1.w)));
        m = fmaxf(m, fmaxf(fmaxf(fmaxf(x2.x, x2.y), fmaxf(x2.z, x2.w)),
                           fmaxf(fmaxf(x3.x, x3.y), fmaxf(x3.z, x3.w))));
#pragma unroll
        for (int o = 16; o; o >>= 1) m = fmaxf(m, __shfl_xor_sync(0xffffffffu, m, o));
        x0.x = __expf(x0.x - m); x0.y = __expf(x0.y - m); x0.z = __expf(x0.z - m); x0.w = __expf(x0.w - m);
        x1.x = __expf(x1.x - m); x1.y = __expf(x1.y - m); x1.z = __expf(x1.z - m); x1.w = __expf(x1.w - m);
        x2.x = __expf(x2.x - m); x2.y = __expf(x2.y - m); x2.z = __expf(x2.z - m); x2.w = __expf(x2.w - m);
        x3.x = __expf(x3.x - m); x3.y = __expf(x3.y - m); x3.z = __expf(x3.z - m); x3.w = __expf(x3.w - m);
        float s = (x0.x + x0.y + x0.z + x0.w) + (x1.x + x1.y + x1.z + x1.w)
                + (x2.x + x2.y + x2.z + x2.w) + (x3.x + x3.y + x3.z + x3.w);
#pragma unroll
        for (int o = 16; o; o >>= 1) s += __shfl_xor_sync(0xffffffffu, s, o);
        float inv = 1.0f / s;
        x0.x *= inv; x0.y *= inv; x0.z *= inv; x0.w *= inv;
        x1.x *= inv; x1.y *= inv; x1.z *= inv; x1.w *= inv;
        x2.x *= inv; x2.y *= inv; x2.z *= inv; x2.w *= inv;
        x3.x *= inv; x3.y *= inv; x3.z *= inv; x3.w *= inv;
        row[lane] = x0; row[lane + 32] = x1; row[lane + 64] = x2; row[lane + 96] = x3;
    }
    __syncthreads();

    // ---- Phase 3: write attn ----------------------------------------------------
    {
        float* arow = attn + ((size_t)bh * TT + t0) * SS;
        for (int i = tid; i < 32 * 128; i += 256) {
            int r = i >> 7, c = i & 127;
            *(float4*)&arow[(size_t)r * SS + c * 4] = *(const float4*)&sc[r * SCP + c * 4];
        }
    }

    // ---- Phase 4: AV (32t x 64d, 256 thr, micro 2t x 4d) -------------------------
    const float* Vg = g_V + (size_t)bh * SS * DH;
    const int tx = tid & 15;    // d/4
    const int tyy = tid >> 4;   // t/2  (0..15)
    unsigned long long acc[2][2];
    acc[0][0] = acc[0][1] = acc[1][0] = acc[1][1] = 0ull;

#pragma unroll 1
    for (int s0 = 0; s0 < SS; s0 += 32) {
        __syncthreads();
        for (int i = tid; i < 512; i += 256) {
            int rr = i >> 4, cc = i & 15;
            *(float4*)&Bs[rr * 68 + cc * 4] = *(const float4*)&Vg[(size_t)(s0 + rr) * DH + cc * 4];
        }
        __syncthreads();
#pragma unroll 8
        for (int kk = 0; kk < 32; kk++) {
            ulonglong2 b2 = *(const ulonglong2*)&Bs[kk * 68 + tx * 4];
            float a0 = sc[(size_t)(tyy * 2) * SCP + s0 + kk];
            float a1 = sc[(size_t)(tyy * 2 + 1) * SCP + s0 + kk];
            unsigned long long aa;
            aa = pack2(a0, a0); acc[0][0] = fma2(aa, b2.x, acc[0][0]); acc[0][1] = fma2(aa, b2.y, acc[0][1]);
            aa = pack2(a1, a1); acc[1][0] = fma2(aa, b2.x, acc[1][0]); acc[1][1] = fma2(aa, b2.y, acc[1][1]);
        }
    }

    {
        const int b = bh >> 2;
#pragma unroll
        for (int i = 0; i < 2; i++) {
            int t = t0 + tyy * 2 + i;
            float2 c01 = unpack2(acc[i][0]);
            float2 c23 = unpack2(acc[i][1]);
            *(float4*)&g_att[((size_t)(b * TT + t)) * DM + h * DH + tx * 4] =
                make_float4(c01.x, c01.y, c23.x, c23.y);
        }
    }
}

// ---------------------------------------------------------------------------
extern "C" void kernel_launch(void* const* d_in, const int* in_sizes, int n_in,
                              void* d_out, int out_size) {
    const float* query = (const float*)d_in[0];
    const float* key   = (const float*)d_in[1];
    const float* value = (const float*)d_in[2];
    const float* w_q   = (const float*)d_in[3];
    const float* w_k   = (const float*)d_in[4];
    const float* w_v   = (const float*)d_in[5];
    const float* v_a   = (const float*)d_in[6];
    const float* w_o   = (const float*)d_in[7];

    float* out  = (float*)d_out;
    float* attn = out + (size_t)BB * TT * DM;

    // Q/K/V projections (one launch, z = which)
    gemm_kernel<<<dim3(32, 4, 3), 256>>>(query, key, value, w_q, w_k, w_v, nullptr, 0);

    // fused additive-attention (scores + softmax + AV)
    const int dyn = (32 * SCP + 32 * 68) * sizeof(float);   // ~74.8 KB
    cudaFuncSetAttribute(attn_fused_kernel,
                         cudaFuncAttributeMaxDynamicSharedMemorySize, dyn);
    attn_fused_kernel<<<dim3(BHN, TT / 32), 256, dyn>>>(v_a, attn);

    // output projection: out = g_att @ w_o.T   (w_o passed via q_in slot)
    gemm_kernel<<<dim3(32, 4, 1), 256>>>(w_o, nullptr, nullptr, nullptr, nullptr, nullptr, out, 3);
}